// round 9
// baseline (speedup 1.0000x reference)
#include <cuda_runtime.h>
#include <cuda_fp16.h>

#define NN   100000
#define FIN  256
#define HDIM 128
#define CDIM 64
#define MAXE 1600000
#define NCSR 148                  // CSR pipeline blocks (must be <= wave-1 residency)
#define GB1  ((NN + 127) / 128)   // gemm1 tiles = 782

// Scratch (static device globals — allocation-free per harness rules)
__device__ int     g_degi[NN];
__device__ int     g_rowptr[NN + 1];
__device__ int     g_bsum[NCSR];
__device__ int     g_boff[NCSR];
__device__ int     g_cursor[NN];
__device__ int     g_esrc[MAXE];            // edge sources grouped by dst (CSR)
__device__ float   g_dis[NN];
__device__ __half2 g_hw1h[NN * HDIM / 2];   // fp16: (x@W1)[v]  (UNSCALED)
__device__ float   g_agg1[NN * HDIM];       // fp32: relu(layer-1 aggregate)
__device__ __half2 g_hw2h[NN * CDIM / 2];   // fp16: dis[v]*(agg1@W2)[v]
__device__ __half2 g_agg2h[NN * CDIM / 2];  // fp16: final h2
__device__ int     g_barc;                  // barrier arrive counter (resets to 0)
__device__ int     g_barg;                  // barrier generation (monotonic)

__device__ __forceinline__ void cp_async16(void* smem, const void* gmem) {
    unsigned s = (unsigned)__cvta_generic_to_shared(smem);
    asm volatile("cp.async.ca.shared.global [%0], [%1], 16;\n" :: "r"(s), "l"(gmem));
}
__device__ __forceinline__ void cp_commit() { asm volatile("cp.async.commit_group;\n"); }
__device__ __forceinline__ void cp_wait0()  { asm volatile("cp.async.wait_group 0;\n" ::: "memory"); }

__device__ __forceinline__ unsigned f2tf32(float f) {
    unsigned u;
    asm("cvt.rna.tf32.f32 %0, %1;\n" : "=r"(u) : "f"(f));
    return u;
}

__device__ __forceinline__ void mma_tf32(float* d, const unsigned* a, const unsigned* b) {
    asm volatile(
        "mma.sync.aligned.m16n8k8.row.col.f32.tf32.tf32.f32 "
        "{%0,%1,%2,%3}, {%4,%5,%6,%7}, {%8,%9}, {%0,%1,%2,%3};\n"
        : "+f"(d[0]), "+f"(d[1]), "+f"(d[2]), "+f"(d[3])
        : "r"(a[0]), "r"(a[1]), "r"(a[2]), "r"(a[3]), "r"(b[0]), "r"(b[1]));
}

__device__ __forceinline__ void u4_to_f8(uint4 u, float* f) {
    float2 t;
    t = __half22float2(*(__half2*)&u.x); f[0] = t.x; f[1] = t.y;
    t = __half22float2(*(__half2*)&u.y); f[2] = t.x; f[3] = t.y;
    t = __half22float2(*(__half2*)&u.z); f[4] = t.x; f[5] = t.y;
    t = __half22float2(*(__half2*)&u.w); f[6] = t.x; f[7] = t.y;
}

// Grid barrier among the NCSR CSR blocks only (all co-resident in wave 1).
__device__ __forceinline__ void csr_barrier() {
    __syncthreads();
    if (threadIdx.x == 0) {
        int gen = atomicAdd(&g_barg, 0);
        __threadfence();
        int t = atomicAdd(&g_barc, 1);
        if (t == NCSR - 1) {
            atomicExch(&g_barc, 0);
            __threadfence();
            atomicAdd(&g_barg, 1);
        } else {
            while (atomicAdd(&g_barg, 0) == gen) { __nanosleep(64); }
        }
    }
    __syncthreads();
}

// ───────────────────────── TF32 tensor-core GEMM body ─────────────────────────
// SCALE_DIS ? C = fp16(dis[row]*(A@B)) : C = fp16(A@B).
// NOTE: g_* pointers must be resolved in DEVICE code (host shadow-symbol trap).
template<int BM, int BN, int BK, int WM, int WN, int NT, bool SCALE_DIS>
__device__ __forceinline__ void mma_body(
    int bx, const float* __restrict__ A, const float* __restrict__ Bg,
    __half2* __restrict__ C, int M, int N, int K)
{
    constexpr int BKp = BK + 4;
    constexpr int BNp = BN + 8;
    __shared__ float As[2][BM][BKp];
    __shared__ float Bs[2][BK][BNp];

    const int tid  = threadIdx.x;
    const int wid  = tid >> 5;
    const int lane = tid & 31;
    const int grp  = lane >> 2;
    const int qi   = lane & 3;
    constexpr int NWN = BN / WN;
    const int warp_m = wid / NWN;
    const int warp_n = wid % NWN;
    constexpr int MF = WM / 16;
    constexpr int NF = WN / 8;

    const int brow = bx * BM;

    float acc[MF][NF][4];
    #pragma unroll
    for (int i = 0; i < MF; i++)
        #pragma unroll
        for (int j = 0; j < NF; j++)
            #pragma unroll
            for (int q = 0; q < 4; q++) acc[i][j][q] = 0.0f;

    constexpr int AIT = (BM * BK / 4) / NT;
    constexpr int BIT = (BK * BN / 4) / NT;

    auto cpA = [&](int buf, int k0) {
        #pragma unroll
        for (int it = 0; it < AIT; it++) {
            int idx  = tid + it * NT;
            int row  = idx / (BK / 4);
            int kc   = (idx % (BK / 4)) * 4;
            int grow = brow + row;
            if (grow > M - 1) grow = M - 1;
            cp_async16(&As[buf][row][kc], A + (long long)grow * K + k0 + kc);
        }
    };
    auto cpB = [&](int buf, int k0) {
        #pragma unroll
        for (int it = 0; it < BIT; it++) {
            int idx = tid + it * NT;
            int kk  = idx / (BN / 4);
            int nc  = (idx % (BN / 4)) * 4;
            cp_async16(&Bs[buf][kk][nc], Bg + (long long)(k0 + kk) * N + nc);
        }
    };
    auto compute = [&](int buf) {
        #pragma unroll
        for (int ks = 0; ks < BK / 8; ks++) {
            int kk = ks * 8;
            unsigned a[MF][4], b[NF][2];
            #pragma unroll
            for (int fm = 0; fm < MF; fm++) {
                const float* ap = &As[buf][warp_m * WM + fm * 16 + grp][kk + qi];
                a[fm][0] = f2tf32(ap[0]);
                a[fm][1] = f2tf32(ap[8 * BKp]);
                a[fm][2] = f2tf32(ap[4]);
                a[fm][3] = f2tf32(ap[8 * BKp + 4]);
            }
            #pragma unroll
            for (int fn = 0; fn < NF; fn++) {
                const float* bp = &Bs[buf][kk + qi][warp_n * WN + fn * 8 + grp];
                b[fn][0] = f2tf32(bp[0]);
                b[fn][1] = f2tf32(bp[4 * BNp]);
            }
            #pragma unroll
            for (int fm = 0; fm < MF; fm++)
                #pragma unroll
                for (int fn = 0; fn < NF; fn++)
                    mma_tf32(acc[fm][fn], a[fm], b[fn]);
        }
    };

    cpA(0, 0); cpB(0, 0); cp_commit();
    cp_wait0(); __syncthreads();

    const int KT = K / BK;
    for (int t = 1; t < KT; t++) {
        cpA(t & 1, t * BK); cpB(t & 1, t * BK); cp_commit();
        compute((t - 1) & 1);
        cp_wait0(); __syncthreads();
    }
    compute((KT - 1) & 1);

    #pragma unroll
    for (int fm = 0; fm < MF; fm++) {
        int r0 = brow + warp_m * WM + fm * 16 + grp;
        int r1 = r0 + 8;
        float d0 = 1.0f, d1 = 1.0f;
        if (SCALE_DIS) {
            d0 = (r0 < M) ? g_dis[r0] : 0.0f;
            d1 = (r1 < M) ? g_dis[r1] : 0.0f;
        }
        #pragma unroll
        for (int fn = 0; fn < NF; fn++) {
            int col = warp_n * WN + fn * 8 + 2 * qi;
            if (r0 < M)
                C[((long long)r0 * N + col) >> 1] =
                    __floats2half2_rn(acc[fm][fn][0] * d0, acc[fm][fn][1] * d0);
            if (r1 < M)
                C[((long long)r1 * N + col) >> 1] =
                    __floats2half2_rn(acc[fm][fn][2] * d1, acc[fm][fn][3] * d1);
        }
    }
}

// ───────────────────────── CSR pipeline (blocks 0..NCSR-1) ─────────────────────
__device__ __forceinline__ void csr_worker(
    int c, const int* __restrict__ src, const int* __restrict__ dst, int E,
    float* __restrict__ out, int SE, int total)
{
    const int tid = threadIdx.x;
    __shared__ int sc[256];

    // Phase 0: zero degree histogram + zero output tail (independent work).
    for (int i = c * 256 + tid; i < NN; i += NCSR * 256) g_degi[i] = 0;
    for (int i = SE + c * 256 + tid; i < total; i += NCSR * 256) out[i] = 0.0f;
    csr_barrier();

    // Phase 1: degree histogram.
    for (int e = c * 256 + tid; e < E; e += NCSR * 256)
        atomicAdd(&g_degi[dst[e]], 1);
    csr_barrier();

    // Phase 2a: per-block chunk sums.
    const int chunk = (NN + NCSR - 1) / NCSR;
    const int lo = c * chunk;
    const int hi = (lo + chunk < NN) ? lo + chunk : NN;
    {
        int s = 0;
        for (int i = lo + tid; i < hi; i += 256) s += g_degi[i];
        sc[tid] = s; __syncthreads();
        #pragma unroll
        for (int o = 128; o; o >>= 1) {
            if (tid < o) sc[tid] += sc[tid + o];
            __syncthreads();
        }
        if (tid == 0) g_bsum[c] = sc[0];
    }
    csr_barrier();

    // Phase 2b: block 0 exclusive-scans the NCSR chunk sums.
    if (c == 0) {
        int v = (tid < NCSR) ? g_bsum[tid] : 0;
        sc[tid] = v; __syncthreads();
        #pragma unroll
        for (int o = 1; o < 256; o <<= 1) {
            int t2 = (tid >= o) ? sc[tid - o] : 0;
            __syncthreads();
            sc[tid] += t2;
            __syncthreads();
        }
        if (tid < NCSR) g_boff[tid] = sc[tid] - v;
    }
    csr_barrier();

    // Phase 2c: rowptr / cursor / dis over the chunk.
    {
        int running = g_boff[c];
        for (int base = lo; base < hi; base += 256) {
            int i = base + tid;
            int d = (i < hi) ? g_degi[i] : 0;
            sc[tid] = d; __syncthreads();
            #pragma unroll
            for (int o = 1; o < 256; o <<= 1) {
                int t2 = (tid >= o) ? sc[tid - o] : 0;
                __syncthreads();
                sc[tid] += t2;
                __syncthreads();
            }
            if (i < hi) {
                int r = running + sc[tid] - d;
                g_rowptr[i] = r;
                g_cursor[i] = r;
                g_dis[i]    = rsqrtf((float)d + 1.0f);
            }
            running += sc[255];
            __syncthreads();
        }
        if (c == 0 && tid == 0) g_rowptr[NN] = E;
    }
    csr_barrier();

    // Phase 3: bin edge sources by dst.
    for (int e = c * 256 + tid; e < E; e += NCSR * 256) {
        int d = dst[e];
        int p = atomicAdd(&g_cursor[d], 1);
        g_esrc[p] = src[e];
    }
}

// ───────────────────────── fused: CSR pipeline ∥ gemm1 ─────────────────────────
__global__ void __launch_bounds__(256, 2)
k_mega(const float* __restrict__ x, const float* __restrict__ W1,
       const int* __restrict__ src, const int* __restrict__ dst, int E,
       float* __restrict__ out, int SE, int total)
{
    if (blockIdx.x < NCSR) {
        csr_worker(blockIdx.x, src, dst, E, out, SE, total);
    } else {
        mma_body<128, 128, 16, 64, 32, 256, false>(
            blockIdx.x - NCSR, x, W1, g_hw1h, NN, HDIM, FIN);
    }
}

// ───────────────────────── gather aggregation ─────────────────────────
// Layer 1: hw1h UNSCALED.  S = dv*h1[v] + Σ_e ds*h1[s];  agg1 = relu(dv*S + b1).
__global__ void k_gather1(const float* __restrict__ b1) {
    int t = blockIdx.x * blockDim.x + threadIdx.x;
    int v = t >> 4, lane = t & 15;
    if (v >= NN) return;
    int beg = g_rowptr[v], end = g_rowptr[v + 1];
    float dv = g_dis[v];
    const uint4* hw = (const uint4*)g_hw1h;   // 16 uint4 per row

    float a[8], a2[8], f[8];
    u4_to_f8(hw[(long long)v * 16 + lane], f);
    #pragma unroll
    for (int i = 0; i < 8; i++) { a[i] = dv * f[i]; a2[i] = 0.f; }

    int p = beg;
    for (; p + 1 < end; p += 2) {
        int sa = __ldg(&g_esrc[p]);
        int sb = __ldg(&g_esrc[p + 1]);
        float da = g_dis[sa], db = g_dis[sb];
        uint4 ua = hw[(long long)sa * 16 + lane];
        uint4 ub = hw[(long long)sb * 16 + lane];
        float fa[8], fb[8];
        u4_to_f8(ua, fa); u4_to_f8(ub, fb);
        #pragma unroll
        for (int i = 0; i < 8; i++) { a[i] += da * fa[i]; a2[i] += db * fb[i]; }
    }
    if (p < end) {
        int sa = __ldg(&g_esrc[p]);
        float da = g_dis[sa];
        float fa[8];
        u4_to_f8(hw[(long long)sa * 16 + lane], fa);
        #pragma unroll
        for (int i = 0; i < 8; i++) a[i] += da * fa[i];
    }
    float4 b0 = ((const float4*)b1)[lane * 2];
    float4 b1v = ((const float4*)b1)[lane * 2 + 1];
    float o[8];
    o[0] = fmaxf(fmaf(dv, a[0] + a2[0], b0.x), 0.f);
    o[1] = fmaxf(fmaf(dv, a[1] + a2[1], b0.y), 0.f);
    o[2] = fmaxf(fmaf(dv, a[2] + a2[2], b0.z), 0.f);
    o[3] = fmaxf(fmaf(dv, a[3] + a2[3], b0.w), 0.f);
    o[4] = fmaxf(fmaf(dv, a[4] + a2[4], b1v.x), 0.f);
    o[5] = fmaxf(fmaf(dv, a[5] + a2[5], b1v.y), 0.f);
    o[6] = fmaxf(fmaf(dv, a[6] + a2[6], b1v.z), 0.f);
    o[7] = fmaxf(fmaf(dv, a[7] + a2[7], b1v.w), 0.f);
    float4* outp = (float4*)(g_agg1 + (long long)v * HDIM + lane * 8);
    outp[0] = make_float4(o[0], o[1], o[2], o[3]);
    outp[1] = make_float4(o[4], o[5], o[6], o[7]);
}

// Layer 2: hw2h pre-scaled by dis.  agg2 = fp16(dv*(hw2[v]+Σ hw2[s]) + b2).
__global__ void k_gather2(const float* __restrict__ b2) {
    int t = blockIdx.x * blockDim.x + threadIdx.x;
    int v = t >> 3, lane = t & 7;
    if (v >= NN) return;
    int beg = g_rowptr[v], end = g_rowptr[v + 1];
    float dv = g_dis[v];
    const uint4* hw = (const uint4*)g_hw2h;   // 8 uint4 per row

    float a[8], a2[8];
    u4_to_f8(hw[(long long)v * 8 + lane], a);
    #pragma unroll
    for (int i = 0; i < 8; i++) a2[i] = 0.f;

    int p = beg;
    for (; p + 1 < end; p += 2) {
        int sa = __ldg(&g_esrc[p]);
        int sb = __ldg(&g_esrc[p + 1]);
        uint4 ua = hw[(long long)sa * 8 + lane];
        uint4 ub = hw[(long long)sb * 8 + lane];
        float fa[8], fb[8];
        u4_to_f8(ua, fa); u4_to_f8(ub, fb);
        #pragma unroll
        for (int i = 0; i < 8; i++) { a[i] += fa[i]; a2[i] += fb[i]; }
    }
    if (p < end) {
        int sa = __ldg(&g_esrc[p]);
        float fa[8];
        u4_to_f8(hw[(long long)sa * 8 + lane], fa);
        #pragma unroll
        for (int i = 0; i < 8; i++) a[i] += fa[i];
    }
    float4 b0 = ((const float4*)b2)[lane * 2];
    float4 b1v = ((const float4*)b2)[lane * 2 + 1];
    float o[8];
    o[0] = fmaf(dv, a[0] + a2[0], b0.x);
    o[1] = fmaf(dv, a[1] + a2[1], b0.y);
    o[2] = fmaf(dv, a[2] + a2[2], b0.z);
    o[3] = fmaf(dv, a[3] + a2[3], b0.w);
    o[4] = fmaf(dv, a[4] + a2[4], b1v.x);
    o[5] = fmaf(dv, a[5] + a2[5], b1v.y);
    o[6] = fmaf(dv, a[6] + a2[6], b1v.z);
    o[7] = fmaf(dv, a[7] + a2[7], b1v.w);
    uint4 u;
    *(__half2*)&u.x = __floats2half2_rn(o[0], o[1]);
    *(__half2*)&u.y = __floats2half2_rn(o[2], o[3]);
    *(__half2*)&u.z = __floats2half2_rn(o[4], o[5]);
    *(__half2*)&u.w = __floats2half2_rn(o[6], o[7]);
    ((uint4*)g_agg2h)[(long long)v * 8 + lane] = u;
}

// ───────────────────────── scoring: 8 lanes/edge, uint4/lane ─────────────────────
__global__ void k_score(const int* __restrict__ pos, const int* __restrict__ neg,
                        int EPn, int SE, float* __restrict__ out)
{
    int t = blockIdx.x * blockDim.x + threadIdx.x;
    int e = t >> 3, lane = t & 7;
    if (e >= SE) return;
    int i, j;
    if (e < EPn) { j = pos[e];       i = pos[e + EPn]; }
    else         { j = neg[e - EPn]; i = neg[e];       }
    const uint4* h4 = (const uint4*)g_agg2h;
    float fa[8], fb[8];
    u4_to_f8(h4[(long long)i * 8 + lane], fa);
    u4_to_f8(h4[(long long)j * 8 + lane], fb);
    float s = fa[0] * fb[0] + fa[1] * fb[1] + fa[2] * fb[2] + fa[3] * fb[3]
            + fa[4] * fb[4] + fa[5] * fb[5] + fa[6] * fb[6] + fa[7] * fb[7];
    #pragma unroll
    for (int o = 4; o; o >>= 1) s += __shfl_xor_sync(0xffffffffu, s, o);
    if (lane == 0) out[e] = s;
}

// ───────────────────────── gemm2 wrapper ─────────────────────────
__global__ void __launch_bounds__(256)
k_gemm2(const float* __restrict__ W2)
{
    mma_body<128, 64, 16, 32, 32, 256, true>(blockIdx.x, g_agg1, W2, g_hw2h,
                                             NN, CDIM, HDIM);
}

extern "C" void kernel_launch(void* const* d_in, const int* in_sizes, int n_in,
                              void* d_out, int out_size)
{
    const float* x   = (const float*)d_in[0];
    // d_in[1] = masked_nodes (unused by the reference output)
    const int*   pos = (const int*)d_in[2];
    const int*   neg = (const int*)d_in[3];
    const int*   ei  = (const int*)d_in[4];
    const float* W1  = (const float*)d_in[5];
    const float* b1  = (const float*)d_in[6];
    const float* W2  = (const float*)d_in[7];
    const float* b2  = (const float*)d_in[8];
    float* out = (float*)d_out;

    const int E   = in_sizes[4] / 2;
    const int EPn = in_sizes[2] / 2;
    const int SE  = 2 * EPn;
    const int* src = ei;
    const int* dst = ei + E;

    // CSR pipeline (148 blocks, internal grid barriers) ∥ gemm1 (782 tiles)
    k_mega<<<NCSR + GB1, 256>>>(x, W1, src, dst, E, out, SE, out_size);

    k_gather1<<<(NN * 16 + 255) / 256, 256>>>(b1);

    k_gemm2<<<(NN + 127) / 128, 256>>>(W2);
    k_gather2<<<(NN * 8 + 255) / 256, 256>>>(b2);

    k_score<<<(SE * 8 + 255) / 256, 256>>>(pos, neg, EPn, SE, out);
}